// round 14
// baseline (speedup 1.0000x reference)
#include <cuda_runtime.h>

// CLUBv2: mi = BETA * sum_d Var_d(y[:, d])
// y: [1024, 256] fp32 row-major. Output: 1 fp32 scalar.
//
//   mi = ( (sum_all y^2)/N - sum_d mu_d^2 ) * BETA
//
// FINAL CHAMPION (benched 6.624/6.624/6.656us: R7, R10, R12).
// GRID=32 x 256, coalesced scalar loads, disjoint per-block plain stores
// (no data atomics — L2 atomic-ALU drain dominates otherwise, see R5/R6),
// ONE acq_rel ticket per block, winner block reduces 32KB in fixed order
// -> bit-deterministic fp32.
// Remaining time is floor-bound: ~2.5-3us launch ramp + ~1.3us serial
// memory chain (DRAM load -> partial store -> ticket -> L2 tail) + ~1us
// harness graph overhead. 13 rounds of structural variants (fixed-point
// REDs, smem combine, grid 8/32/128, float2 fusion) all land >= this.

#define N_ROWS 1024
#define N_COLS 256
#define GRID   32
#define ROWS_PER_BLOCK (N_ROWS / GRID)   // 32
#define BETA_F 0.001f

__device__ float        g_ps[GRID * N_COLS];  // per-block column sums (32KB)
__device__ float        g_qp[GRID];           // per-block sum-of-squares
__device__ unsigned int g_ticket = 0;
// g_ps/g_qp fully overwritten every launch; winner resets g_ticket ->
// every graph replay identical. Deterministic.

__device__ __forceinline__ unsigned int atom_add_acq_rel(unsigned int* addr,
                                                         unsigned int v) {
    unsigned int old;
    asm volatile("atom.acq_rel.gpu.global.add.u32 %0, [%1], %2;"
                 : "=r"(old) : "l"(addr), "r"(v) : "memory");
    return old;
}

__global__ void __launch_bounds__(N_COLS, 1)
club_var_kernel(const float* __restrict__ y, float* __restrict__ out) {
    const int t    = threadIdx.x;   // column index 0..255
    const int b    = blockIdx.x;
    const int lane = t & 31;
    const int warp = t >> 5;

    // Phase 1: 32 rows per block per column, coalesced scalar loads,
    // fully unrolled -> deep MLP, one memory-latency exposure.
    float s = 0.0f, q = 0.0f;
    const float* p = y + (size_t)b * ROWS_PER_BLOCK * N_COLS + t;
    #pragma unroll
    for (int r = 0; r < ROWS_PER_BLOCK; ++r) {
        float v = p[r * N_COLS];
        s += v;
        q = fmaf(v, v, q);
    }

    // Per-block column partial: ONE plain store, disjoint slot.
    __stcg(&g_ps[b * N_COLS + t], s);

    // Q: warp shuffle-reduce (fixed order), 8 partials through smem.
    #pragma unroll
    for (int off = 16; off > 0; off >>= 1)
        q += __shfl_down_sync(0xFFFFFFFFu, q, off);
    __shared__ float sm_q[8];
    __shared__ bool  is_last;
    if (lane == 0) sm_q[warp] = q;

    // Ticket: bar.sync orders all stores intra-block; t0 stores the block's
    // Q partial, then its gpu-scope acq_rel release publishes everything.
    __syncthreads();
    if (t == 0) {
        float qb = ((sm_q[0] + sm_q[1]) + (sm_q[2] + sm_q[3]))
                 + ((sm_q[4] + sm_q[5]) + (sm_q[6] + sm_q[7]));
        __stcg(&g_qp[b], qb);
        is_last = (atom_add_acq_rel(&g_ticket, 1u) == (unsigned)(GRID - 1));
    }
    __syncthreads();

    if (is_last) {
        // Tail: 32KB from L2, coalesced (warp instr = 1 x 128B line).
        // Thread t sums column t across 32 blocks: 4 independent
        // accumulators (max serial chain 8), fixed order -> deterministic.
        float a0 = 0.f, a1 = 0.f, a2 = 0.f, a3 = 0.f;
        #pragma unroll
        for (int bb = 0; bb < GRID; bb += 4) {
            a0 += __ldcg(&g_ps[(bb + 0) * N_COLS + t]);
            a1 += __ldcg(&g_ps[(bb + 1) * N_COLS + t]);
            a2 += __ldcg(&g_ps[(bb + 2) * N_COLS + t]);
            a3 += __ldcg(&g_ps[(bb + 3) * N_COLS + t]);
        }
        const float S = (a0 + a1) + (a2 + a3);

        // Warp 0 picks up the 32 Q partials in parallel (independent path).
        float qv = 0.0f;
        if (warp == 0) qv = __ldcg(&g_qp[lane]);

        const float mu = S * (1.0f / (float)N_ROWS);
        float acc = mu * mu;                 // this thread's mu_d^2

        // Fixed-order reduction of sum_d mu_d^2.
        #pragma unroll
        for (int off = 16; off > 0; off >>= 1)
            acc += __shfl_down_sync(0xFFFFFFFFu, acc, off);
        __shared__ float wsum[8];
        if (lane == 0) wsum[warp] = acc;
        __syncthreads();

        if (warp == 0) {
            // Qtot: fixed-order shuffle tree over the 32 partials.
            #pragma unroll
            for (int off = 16; off > 0; off >>= 1)
                qv += __shfl_down_sync(0xFFFFFFFFu, qv, off);

            float v = (lane < 8) ? wsum[lane] : 0.0f;
            #pragma unroll
            for (int off = 4; off > 0; off >>= 1)
                v += __shfl_down_sync(0xFFFFFFFFu, v, off);

            if (lane == 0) {
                const float EQ = qv * (1.0f / (float)N_ROWS); // sum_d E[y^2]_d
                out[0] = (EQ - v) * BETA_F;
                g_ticket = 0;   // reset for next graph replay
            }
        }
    }
}

extern "C" void kernel_launch(void* const* d_in, const int* in_sizes, int n_in,
                              void* d_out, int out_size) {
    (void)in_sizes; (void)n_in; (void)out_size;
    const float* y = (const float*)d_in[0];
    float* out = (float*)d_out;
    club_var_kernel<<<GRID, N_COLS>>>(y, out);
}

// round 15
// speedup vs baseline: 1.1635x; 1.1635x over previous
#include <cuda_runtime.h>

// CLUBv2: mi = BETA * sum_d Var_d(y[:, d])
// y: [1024, 256] fp32 row-major. Output: 1 fp32 scalar.
//
//   mi = ( (sum_all y^2)/N - sum_d mu_d^2 ) * BETA
//
// FINAL CHAMPION — benched 6.624 / 6.624 / 6.656 / 7.744us (byte-identical
// runs; +-0.6us run-to-run noise). GRID=32 x 256, coalesced scalar loads,
// disjoint per-block plain stores (no data atomics — L2 atomic-ALU drain
// dominates otherwise, measured R5/R6), ONE acq_rel ticket per block,
// winner block reduces 32KB in fixed order -> bit-deterministic fp32.
//
// 14 rounds of structural variants (fixed-point int64 REDs, smem combine,
// grid 8/32/128, float2 fusion, warp-granular tickets, reorderings) all
// measured >= this. Remaining time is floor-bound: ~2.8us launch ramp +
// ~1.3us serial memory chain (DRAM load -> partial store -> ticket ->
// L2 tail) + ~1us harness graph-replay overhead.

#define N_ROWS 1024
#define N_COLS 256
#define GRID   32
#define ROWS_PER_BLOCK (N_ROWS / GRID)   // 32
#define BETA_F 0.001f

__device__ float        g_ps[GRID * N_COLS];  // per-block column sums (32KB)
__device__ float        g_qp[GRID];           // per-block sum-of-squares
__device__ unsigned int g_ticket = 0;
// g_ps/g_qp fully overwritten every launch; winner resets g_ticket ->
// every graph replay identical. Deterministic.

__device__ __forceinline__ unsigned int atom_add_acq_rel(unsigned int* addr,
                                                         unsigned int v) {
    unsigned int old;
    asm volatile("atom.acq_rel.gpu.global.add.u32 %0, [%1], %2;"
                 : "=r"(old) : "l"(addr), "r"(v) : "memory");
    return old;
}

__global__ void __launch_bounds__(N_COLS, 1)
club_var_kernel(const float* __restrict__ y, float* __restrict__ out) {
    const int t    = threadIdx.x;   // column index 0..255
    const int b    = blockIdx.x;
    const int lane = t & 31;
    const int warp = t >> 5;

    // Phase 1: 32 rows per block per column, coalesced scalar loads,
    // fully unrolled -> deep MLP, one memory-latency exposure.
    float s = 0.0f, q = 0.0f;
    const float* p = y + (size_t)b * ROWS_PER_BLOCK * N_COLS + t;
    #pragma unroll
    for (int r = 0; r < ROWS_PER_BLOCK; ++r) {
        float v = p[r * N_COLS];
        s += v;
        q = fmaf(v, v, q);
    }

    // Per-block column partial: ONE plain store, disjoint slot.
    __stcg(&g_ps[b * N_COLS + t], s);

    // Q: warp shuffle-reduce (fixed order), 8 partials through smem.
    #pragma unroll
    for (int off = 16; off > 0; off >>= 1)
        q += __shfl_down_sync(0xFFFFFFFFu, q, off);
    __shared__ float sm_q[8];
    __shared__ bool  is_last;
    if (lane == 0) sm_q[warp] = q;

    // Ticket: bar.sync orders all stores intra-block; t0 stores the block's
    // Q partial, then its gpu-scope acq_rel release publishes everything.
    __syncthreads();
    if (t == 0) {
        float qb = ((sm_q[0] + sm_q[1]) + (sm_q[2] + sm_q[3]))
                 + ((sm_q[4] + sm_q[5]) + (sm_q[6] + sm_q[7]));
        __stcg(&g_qp[b], qb);
        is_last = (atom_add_acq_rel(&g_ticket, 1u) == (unsigned)(GRID - 1));
    }
    __syncthreads();

    if (is_last) {
        // Tail: 32KB from L2, coalesced (warp instr = 1 x 128B line).
        // Thread t sums column t across 32 blocks: 4 independent
        // accumulators (max serial chain 8), fixed order -> deterministic.
        float a0 = 0.f, a1 = 0.f, a2 = 0.f, a3 = 0.f;
        #pragma unroll
        for (int bb = 0; bb < GRID; bb += 4) {
            a0 += __ldcg(&g_ps[(bb + 0) * N_COLS + t]);
            a1 += __ldcg(&g_ps[(bb + 1) * N_COLS + t]);
            a2 += __ldcg(&g_ps[(bb + 2) * N_COLS + t]);
            a3 += __ldcg(&g_ps[(bb + 3) * N_COLS + t]);
        }
        const float S = (a0 + a1) + (a2 + a3);

        // Warp 0 picks up the 32 Q partials in parallel (independent path).
        float qv = 0.0f;
        if (warp == 0) qv = __ldcg(&g_qp[lane]);

        const float mu = S * (1.0f / (float)N_ROWS);
        float acc = mu * mu;                 // this thread's mu_d^2

        // Fixed-order reduction of sum_d mu_d^2.
        #pragma unroll
        for (int off = 16; off > 0; off >>= 1)
            acc += __shfl_down_sync(0xFFFFFFFFu, acc, off);
        __shared__ float wsum[8];
        if (lane == 0) wsum[warp] = acc;
        __syncthreads();

        if (warp == 0) {
            // Qtot: fixed-order shuffle tree over the 32 partials.
            #pragma unroll
            for (int off = 16; off > 0; off >>= 1)
                qv += __shfl_down_sync(0xFFFFFFFFu, qv, off);

            float v = (lane < 8) ? wsum[lane] : 0.0f;
            #pragma unroll
            for (int off = 4; off > 0; off >>= 1)
                v += __shfl_down_sync(0xFFFFFFFFu, v, off);

            if (lane == 0) {
                const float EQ = qv * (1.0f / (float)N_ROWS); // sum_d E[y^2]_d
                out[0] = (EQ - v) * BETA_F;
                g_ticket = 0;   // reset for next graph replay
            }
        }
    }
}

extern "C" void kernel_launch(void* const* d_in, const int* in_sizes, int n_in,
                              void* d_out, int out_size) {
    (void)in_sizes; (void)n_in; (void)out_size;
    const float* y = (const float*)d_in[0];
    float* out = (float*)d_out;
    club_var_kernel<<<GRID, N_COLS>>>(y, out);
}